// round 12
// baseline (speedup 1.0000x reference)
#include <cuda_runtime.h>

#define HIDDEN 2048
#define HEADS  16
#define HDIM   128
#define BATCH  4
#define SEQ    2048
#define MROWS  (BATCH*SEQ)        /* 8192 */
#define NQKV   (3*HIDDEN)         /* 6144 */

// ---------------- scratch (device globals; no runtime allocation) ----------
__device__ float g_qkv[(size_t)MROWS * NQKV];                 // 201 MB
__device__ float g_q  [(size_t)BATCH*HEADS*SEQ*HDIM];         // 67 MB  [B,H,L,D]
__device__ float g_k  [(size_t)BATCH*HEADS*SEQ*HDIM];
__device__ float g_v  [(size_t)BATCH*HEADS*SEQ*HDIM];
__device__ float g_ao [(size_t)MROWS * HIDDEN];               // [B,L,H*D]

// ============================================================================
// SGEMM (NT): C[m][n] = sum_k A[m*K+k] * B[n*K+k]
// 128x128 block tile, BK=16, 256 threads, 8x8 per-thread register tile.
// Both A and B tiles stored k-major-transposed in smem: s[kk][row].
// Requires M%128==0, N%128==0, K%16==0 (true for all our shapes).
// ============================================================================
__global__ __launch_bounds__(256, 2)
void sgemm_nt(const float* __restrict__ A, const float* __restrict__ B,
              float* __restrict__ C, int M, int N, int K)
{
    __shared__ float As[16 * 128];
    __shared__ float Bs[16 * 128];

    const int tid = threadIdx.x;
    const int ty  = tid >> 4;      // 0..15
    const int tx  = tid & 15;      // 0..15
    const int m0  = blockIdx.y * 128;
    const int n0  = blockIdx.x * 128;

    float acc[8][8];
#pragma unroll
    for (int i = 0; i < 8; ++i)
#pragma unroll
        for (int j = 0; j < 8; ++j) acc[i][j] = 0.f;

    for (int k0 = 0; k0 < K; k0 += 16) {
        // cooperative load: tile is [128 rows][16 k]; 512 float4 per tensor
#pragma unroll
        for (int t = 0; t < 2; ++t) {
            int idx = tid * 2 + t;
            int row = idx >> 2;
            int kq  = idx & 3;
            float4 av = *(const float4*)(A + (size_t)(m0 + row) * K + k0 + kq * 4);
            float4 bv = *(const float4*)(B + (size_t)(n0 + row) * K + k0 + kq * 4);
            As[(kq*4+0)*128 + row] = av.x; As[(kq*4+1)*128 + row] = av.y;
            As[(kq*4+2)*128 + row] = av.z; As[(kq*4+3)*128 + row] = av.w;
            Bs[(kq*4+0)*128 + row] = bv.x; Bs[(kq*4+1)*128 + row] = bv.y;
            Bs[(kq*4+2)*128 + row] = bv.z; Bs[(kq*4+3)*128 + row] = bv.w;
        }
        __syncthreads();
#pragma unroll
        for (int kk = 0; kk < 16; ++kk) {
            float4 a0 = *(const float4*)(As + kk*128 + ty*4);
            float4 a1 = *(const float4*)(As + kk*128 + 64 + ty*4);
            float4 b0 = *(const float4*)(Bs + kk*128 + tx*4);
            float4 b1 = *(const float4*)(Bs + kk*128 + 64 + tx*4);
            float av[8] = {a0.x,a0.y,a0.z,a0.w,a1.x,a1.y,a1.z,a1.w};
            float bv[8] = {b0.x,b0.y,b0.z,b0.w,b1.x,b1.y,b1.z,b1.w};
#pragma unroll
            for (int i = 0; i < 8; ++i)
#pragma unroll
                for (int j = 0; j < 8; ++j)
                    acc[i][j] += av[i] * bv[j];
        }
        __syncthreads();
    }

#pragma unroll
    for (int i = 0; i < 8; ++i) {
        int r = m0 + ((i < 4) ? (ty*4 + i) : (60 + ty*4 + i));  // i>=4 -> 64+ty*4+(i-4)
#pragma unroll
        for (int jg = 0; jg < 2; ++jg) {
            float4 v = make_float4(acc[i][jg*4+0], acc[i][jg*4+1],
                                   acc[i][jg*4+2], acc[i][jg*4+3]);
            *(float4*)(C + (size_t)r * N + n0 + jg*64 + tx*4) = v;
        }
    }
}

// ============================================================================
// RoPE + split qkv[B,L,3*HIDDEN] -> Q,K (rotated), V  in [B,H,L,D]
// One thread per (b,h,l,d0) with d0 in [0,64): handles the paired element too.
// ============================================================================
__global__ __launch_bounds__(256)
void rope_split(const float* __restrict__ qkv,
                const float* __restrict__ cs, const float* __restrict__ sn,
                float* __restrict__ Q, float* __restrict__ Kd,
                float* __restrict__ V)
{
    int idx = blockIdx.x * blockDim.x + threadIdx.x;     // B*L*H*64 threads
    int d0 = idx & 63;
    int h  = (idx >> 6) & 15;
    int l  = (idx >> 10) & 2047;
    int b  = idx >> 21;

    const float* row = qkv + (size_t)(b * SEQ + l) * NQKV;
    float c0 = cs[l*HDIM + d0],      s0 = sn[l*HDIM + d0];
    float c1 = cs[l*HDIM + d0 + 64], s1 = sn[l*HDIM + d0 + 64];

    size_t obase = ((size_t)((b*HEADS + h) * SEQ + l)) * HDIM;

    float q0 = row[h*HDIM + d0], q1 = row[h*HDIM + d0 + 64];
    Q[obase + d0]      = q0 * c0 - q1 * s0;
    Q[obase + d0 + 64] = q1 * c1 + q0 * s1;

    float k0 = row[HIDDEN + h*HDIM + d0], k1 = row[HIDDEN + h*HDIM + d0 + 64];
    Kd[obase + d0]      = k0 * c0 - k1 * s0;
    Kd[obase + d0 + 64] = k1 * c1 + k0 * s1;

    V[obase + d0]      = row[2*HIDDEN + h*HDIM + d0];
    V[obase + d0 + 64] = row[2*HIDDEN + h*HDIM + d0 + 64];
}

// ============================================================================
// Flash attention, fp32. grid = (SEQ/128, B*H), 256 threads.
// Q tile 128 rows, KV tile 128 rows, D=128 streamed with BK=16 for S = Q K^T.
// Online softmax; P staged transposed in smem (pitch 132 to cut STS conflicts);
// O = P V accumulated in registers (8x8/thread). Output written in [B,L,H,D].
// Dynamic smem = 149504 B.
// ============================================================================
#define PS_PITCH 132
#define ATT_SMEM ((2*16*128 + 128*PS_PITCH + 128*128) * 4)

__global__ __launch_bounds__(256)
void attn_kernel(const float* __restrict__ Q, const float* __restrict__ K,
                 const float* __restrict__ V, float* __restrict__ AO)
{
    extern __shared__ float sm[];
    float* As = sm;                       // [16][128]  Q d-slice, transposed
    float* Bs = As + 16*128;              // [16][128]  K d-slice, transposed
    float* Ps = Bs + 16*128;              // [128][132] P transposed: Ps[k][r]
    float* Vs = Ps + 128*PS_PITCH;        // [128][128] V tile: Vs[k][c]

    const int bh = blockIdx.y;
    const int qt = blockIdx.x;
    const float* Qp = Q + (size_t)bh * SEQ * HDIM + (size_t)qt * 128 * HDIM;
    const float* Kp = K + (size_t)bh * SEQ * HDIM;
    const float* Vp = V + (size_t)bh * SEQ * HDIM;

    const int tid = threadIdx.x;
    const int ty  = tid >> 4;
    const int tx  = tid & 15;

    const float scale = 0.08838834764831845f;   // 1/sqrt(128)

    float m[8], l[8], o[8][8];
#pragma unroll
    for (int i = 0; i < 8; ++i) {
        m[i] = -1e30f; l[i] = 0.f;
#pragma unroll
        for (int j = 0; j < 8; ++j) o[i][j] = 0.f;
    }

    for (int kt = 0; kt < SEQ; kt += 128) {
        // ---------------- S = Q K^T (this 128x128 tile) ----------------
        float s[8][8];
#pragma unroll
        for (int i = 0; i < 8; ++i)
#pragma unroll
            for (int j = 0; j < 8; ++j) s[i][j] = 0.f;

        for (int d0 = 0; d0 < HDIM; d0 += 16) {
#pragma unroll
            for (int t = 0; t < 2; ++t) {
                int idx = tid * 2 + t;
                int row = idx >> 2;
                int kq  = idx & 3;
                float4 qa = *(const float4*)(Qp + (size_t)row * HDIM + d0 + kq*4);
                float4 kb = *(const float4*)(Kp + (size_t)(kt + row) * HDIM + d0 + kq*4);
                As[(kq*4+0)*128 + row] = qa.x; As[(kq*4+1)*128 + row] = qa.y;
                As[(kq*4+2)*128 + row] = qa.z; As[(kq*4+3)*128 + row] = qa.w;
                Bs[(kq*4+0)*128 + row] = kb.x; Bs[(kq*4+1)*128 + row] = kb.y;
                Bs[(kq*4+2)*128 + row] = kb.z; Bs[(kq*4+3)*128 + row] = kb.w;
            }
            __syncthreads();
#pragma unroll
            for (int kk = 0; kk < 16; ++kk) {
                float4 a0 = *(const float4*)(As + kk*128 + ty*4);
                float4 a1 = *(const float4*)(As + kk*128 + 64 + ty*4);
                float4 b0 = *(const float4*)(Bs + kk*128 + tx*4);
                float4 b1 = *(const float4*)(Bs + kk*128 + 64 + tx*4);
                float av[8] = {a0.x,a0.y,a0.z,a0.w,a1.x,a1.y,a1.z,a1.w};
                float bv[8] = {b0.x,b0.y,b0.z,b0.w,b1.x,b1.y,b1.z,b1.w};
#pragma unroll
                for (int i = 0; i < 8; ++i)
#pragma unroll
                    for (int j = 0; j < 8; ++j)
                        s[i][j] += av[i] * bv[j];
            }
            __syncthreads();
        }

        // ---------------- online softmax (rows owned by ty; reduce over tx) --
#pragma unroll
        for (int i = 0; i < 8; ++i) {
            float rmax = -1e30f;
#pragma unroll
            for (int j = 0; j < 8; ++j) { s[i][j] *= scale; rmax = fmaxf(rmax, s[i][j]); }
#pragma unroll
            for (int off = 8; off > 0; off >>= 1)
                rmax = fmaxf(rmax, __shfl_xor_sync(0xffffffffu, rmax, off, 16));
            float mnew = fmaxf(m[i], rmax);
            float corr = __expf(m[i] - mnew);
            float rsum = 0.f;
#pragma unroll
            for (int j = 0; j < 8; ++j) { s[i][j] = __expf(s[i][j] - mnew); rsum += s[i][j]; }
#pragma unroll
            for (int off = 8; off > 0; off >>= 1)
                rsum += __shfl_xor_sync(0xffffffffu, rsum, off, 16);
            m[i] = mnew;
            l[i] = l[i] * corr + rsum;
#pragma unroll
            for (int j = 0; j < 8; ++j) o[i][j] *= corr;
        }

        // ---------------- stage P^T to smem + load V tile ----------------
#pragma unroll
        for (int jj = 0; jj < 8; ++jj) {
            int c = (jj < 4) ? (tx*4 + jj) : (60 + tx*4 + jj);
            float4 p0 = make_float4(s[0][jj], s[1][jj], s[2][jj], s[3][jj]);
            float4 p1 = make_float4(s[4][jj], s[5][jj], s[6][jj], s[7][jj]);
            *(float4*)(Ps + c*PS_PITCH + ty*4)      = p0;
            *(float4*)(Ps + c*PS_PITCH + 64 + ty*4) = p1;
        }
#pragma unroll
        for (int t = 0; t < 16; ++t) {                 // 4096 float4 / 256 thr
            int idx = t * 256 + tid;
            int row = idx >> 5;
            int cq  = idx & 31;
            *(float4*)(Vs + row*128 + cq*4) =
                *(const float4*)(Vp + (size_t)(kt + row) * HDIM + cq*4);
        }
        __syncthreads();

        // ---------------- O += P V ----------------
#pragma unroll 4
        for (int kk = 0; kk < 128; ++kk) {
            float4 a0 = *(const float4*)(Ps + kk*PS_PITCH + ty*4);
            float4 a1 = *(const float4*)(Ps + kk*PS_PITCH + 64 + ty*4);
            float4 b0 = *(const float4*)(Vs + kk*128 + tx*4);
            float4 b1 = *(const float4*)(Vs + kk*128 + 64 + tx*4);
            float av[8] = {a0.x,a0.y,a0.z,a0.w,a1.x,a1.y,a1.z,a1.w};
            float bv[8] = {b0.x,b0.y,b0.z,b0.w,b1.x,b1.y,b1.z,b1.w};
#pragma unroll
            for (int i = 0; i < 8; ++i)
#pragma unroll
                for (int j = 0; j < 8; ++j)
                    o[i][j] += av[i] * bv[j];
        }
        __syncthreads();
    }

    // ---------------- finalize & write to [B, L, H, D] ----------------
    const int b = bh >> 4, h = bh & 15;
#pragma unroll
    for (int i = 0; i < 8; ++i) {
        int rloc = (i < 4) ? (ty*4 + i) : (60 + ty*4 + i);
        int lg = qt * 128 + rloc;
        float inv = 1.f / l[i];
        size_t base = ((size_t)((b * SEQ + lg) * HEADS + h)) * HDIM;
#pragma unroll
        for (int jg = 0; jg < 2; ++jg) {
            float4 v4 = make_float4(o[i][jg*4+0]*inv, o[i][jg*4+1]*inv,
                                    o[i][jg*4+2]*inv, o[i][jg*4+3]*inv);
            *(float4*)(AO + base + jg*64 + tx*4) = v4;
        }
    }
}

// ============================================================================
// launch
// ============================================================================
extern "C" void kernel_launch(void* const* d_in, const int* in_sizes, int n_in,
                              void* d_out, int out_size)
{
    (void)in_sizes; (void)n_in; (void)out_size;
    const float* x    = (const float*)d_in[0];
    const float* cs   = (const float*)d_in[1];
    const float* sn   = (const float*)d_in[2];
    const float* wqkv = (const float*)d_in[3];
    const float* wout = (const float*)d_in[4];
    float* out = (float*)d_out;

    float *qkv, *q, *k, *v, *ao;
    cudaGetSymbolAddress((void**)&qkv, g_qkv);
    cudaGetSymbolAddress((void**)&q,   g_q);
    cudaGetSymbolAddress((void**)&k,   g_k);
    cudaGetSymbolAddress((void**)&v,   g_v);
    cudaGetSymbolAddress((void**)&ao,  g_ao);

    cudaFuncSetAttribute(attn_kernel,
                         cudaFuncAttributeMaxDynamicSharedMemorySize, ATT_SMEM);

    dim3 blk(256);
    // 1) qkv = x @ w_qkv^T   [8192, 6144]
    sgemm_nt<<<dim3(NQKV/128, MROWS/128), blk>>>(x, wqkv, qkv, MROWS, NQKV, HIDDEN);
    // 2) RoPE + split to [B,H,L,D]
    rope_split<<<(BATCH*SEQ*HEADS*64)/256, blk>>>(qkv, cs, sn, q, k, v);
    // 3) attention -> [B,L,H*D]
    attn_kernel<<<dim3(SEQ/128, BATCH*HEADS), blk, ATT_SMEM>>>(q, k, v, ao);
    // 4) out = ao @ w_out^T
    sgemm_nt<<<dim3(HIDDEN/128, MROWS/128), blk>>>(ao, wout, out, MROWS, HIDDEN, HIDDEN);
}

// round 13
// speedup vs baseline: 1.0002x; 1.0002x over previous
#include <cuda_runtime.h>

#define HIDDEN 2048
#define HEADS  16
#define HDIM   128
#define BATCH  4
#define SEQ    2048
#define MROWS  (BATCH*SEQ)        /* 8192 */
#define NQKV   (3*HIDDEN)         /* 6144 */

// ---------------- scratch (device globals; no runtime allocation) ----------
__device__ float g_qkv[(size_t)MROWS * NQKV];                 // 201 MB
__device__ float g_q  [(size_t)BATCH*HEADS*SEQ*HDIM];         // 67 MB  [B,H,L,D]
__device__ float g_k  [(size_t)BATCH*HEADS*SEQ*HDIM];
__device__ float g_v  [(size_t)BATCH*HEADS*SEQ*HDIM];
__device__ float g_ao [(size_t)MROWS * HIDDEN];               // [B,L,H*D]

// ============================================================================
// SGEMM (NT): C[m][n] = sum_k A[m*K+k] * B[n*K+k]
// 128x128 block tile, BK=16, 256 threads, 8x8 per-thread register tile.
// Both A and B tiles stored k-major-transposed in smem: s[kk][row].
// Requires M%128==0, N%128==0, K%16==0 (true for all our shapes).
// ============================================================================
__global__ __launch_bounds__(256, 2)
void sgemm_nt(const float* __restrict__ A, const float* __restrict__ B,
              float* __restrict__ C, int M, int N, int K)
{
    __shared__ float As[16 * 128];
    __shared__ float Bs[16 * 128];

    const int tid = threadIdx.x;
    const int ty  = tid >> 4;      // 0..15
    const int tx  = tid & 15;      // 0..15
    const int m0  = blockIdx.y * 128;
    const int n0  = blockIdx.x * 128;

    float acc[8][8];
#pragma unroll
    for (int i = 0; i < 8; ++i)
#pragma unroll
        for (int j = 0; j < 8; ++j) acc[i][j] = 0.f;

    for (int k0 = 0; k0 < K; k0 += 16) {
        // cooperative load: tile is [128 rows][16 k]; 512 float4 per tensor
#pragma unroll
        for (int t = 0; t < 2; ++t) {
            int idx = tid * 2 + t;
            int row = idx >> 2;
            int kq  = idx & 3;
            float4 av = *(const float4*)(A + (size_t)(m0 + row) * K + k0 + kq * 4);
            float4 bv = *(const float4*)(B + (size_t)(n0 + row) * K + k0 + kq * 4);
            As[(kq*4+0)*128 + row] = av.x; As[(kq*4+1)*128 + row] = av.y;
            As[(kq*4+2)*128 + row] = av.z; As[(kq*4+3)*128 + row] = av.w;
            Bs[(kq*4+0)*128 + row] = bv.x; Bs[(kq*4+1)*128 + row] = bv.y;
            Bs[(kq*4+2)*128 + row] = bv.z; Bs[(kq*4+3)*128 + row] = bv.w;
        }
        __syncthreads();
#pragma unroll
        for (int kk = 0; kk < 16; ++kk) {
            float4 a0 = *(const float4*)(As + kk*128 + ty*4);
            float4 a1 = *(const float4*)(As + kk*128 + 64 + ty*4);
            float4 b0 = *(const float4*)(Bs + kk*128 + tx*4);
            float4 b1 = *(const float4*)(Bs + kk*128 + 64 + tx*4);
            float av[8] = {a0.x,a0.y,a0.z,a0.w,a1.x,a1.y,a1.z,a1.w};
            float bv[8] = {b0.x,b0.y,b0.z,b0.w,b1.x,b1.y,b1.z,b1.w};
#pragma unroll
            for (int i = 0; i < 8; ++i)
#pragma unroll
                for (int j = 0; j < 8; ++j)
                    acc[i][j] += av[i] * bv[j];
        }
        __syncthreads();
    }

#pragma unroll
    for (int i = 0; i < 8; ++i) {
        int r = m0 + ((i < 4) ? (ty*4 + i) : (60 + ty*4 + i));  // i>=4 -> 64+ty*4+(i-4)
#pragma unroll
        for (int jg = 0; jg < 2; ++jg) {
            float4 v = make_float4(acc[i][jg*4+0], acc[i][jg*4+1],
                                   acc[i][jg*4+2], acc[i][jg*4+3]);
            *(float4*)(C + (size_t)r * N + n0 + jg*64 + tx*4) = v;
        }
    }
}

// ============================================================================
// RoPE + split qkv[B,L,3*HIDDEN] -> Q,K (rotated), V  in [B,H,L,D]
// One thread per (b,h,l,d0) with d0 in [0,64): handles the paired element too.
// ============================================================================
__global__ __launch_bounds__(256)
void rope_split(const float* __restrict__ qkv,
                const float* __restrict__ cs, const float* __restrict__ sn,
                float* __restrict__ Q, float* __restrict__ Kd,
                float* __restrict__ V)
{
    int idx = blockIdx.x * blockDim.x + threadIdx.x;     // B*L*H*64 threads
    int d0 = idx & 63;
    int h  = (idx >> 6) & 15;
    int l  = (idx >> 10) & 2047;
    int b  = idx >> 21;

    const float* row = qkv + (size_t)(b * SEQ + l) * NQKV;
    float c0 = cs[l*HDIM + d0],      s0 = sn[l*HDIM + d0];
    float c1 = cs[l*HDIM + d0 + 64], s1 = sn[l*HDIM + d0 + 64];

    size_t obase = ((size_t)((b*HEADS + h) * SEQ + l)) * HDIM;

    float q0 = row[h*HDIM + d0], q1 = row[h*HDIM + d0 + 64];
    Q[obase + d0]      = q0 * c0 - q1 * s0;
    Q[obase + d0 + 64] = q1 * c1 + q0 * s1;

    float k0 = row[HIDDEN + h*HDIM + d0], k1 = row[HIDDEN + h*HDIM + d0 + 64];
    Kd[obase + d0]      = k0 * c0 - k1 * s0;
    Kd[obase + d0 + 64] = k1 * c1 + k0 * s1;

    V[obase + d0]      = row[2*HIDDEN + h*HDIM + d0];
    V[obase + d0 + 64] = row[2*HIDDEN + h*HDIM + d0 + 64];
}

// ============================================================================
// Flash attention, fp32. grid = (SEQ/128, B*H), 256 threads.
// Q tile 128 rows, KV tile 128 rows, D=128 streamed with BK=16 for S = Q K^T.
// Online softmax; P staged transposed in smem (pitch 132 to cut STS conflicts);
// O = P V accumulated in registers (8x8/thread). Output written in [B,L,H,D].
// Dynamic smem = 149504 B.
// ============================================================================
#define PS_PITCH 132
#define ATT_SMEM ((2*16*128 + 128*PS_PITCH + 128*128) * 4)

__global__ __launch_bounds__(256)
void attn_kernel(const float* __restrict__ Q, const float* __restrict__ K,
                 const float* __restrict__ V, float* __restrict__ AO)
{
    extern __shared__ float sm[];
    float* As = sm;                       // [16][128]  Q d-slice, transposed
    float* Bs = As + 16*128;              // [16][128]  K d-slice, transposed
    float* Ps = Bs + 16*128;              // [128][132] P transposed: Ps[k][r]
    float* Vs = Ps + 128*PS_PITCH;        // [128][128] V tile: Vs[k][c]

    const int bh = blockIdx.y;
    const int qt = blockIdx.x;
    const float* Qp = Q + (size_t)bh * SEQ * HDIM + (size_t)qt * 128 * HDIM;
    const float* Kp = K + (size_t)bh * SEQ * HDIM;
    const float* Vp = V + (size_t)bh * SEQ * HDIM;

    const int tid = threadIdx.x;
    const int ty  = tid >> 4;
    const int tx  = tid & 15;

    const float scale = 0.08838834764831845f;   // 1/sqrt(128)

    float m[8], l[8], o[8][8];
#pragma unroll
    for (int i = 0; i < 8; ++i) {
        m[i] = -1e30f; l[i] = 0.f;
#pragma unroll
        for (int j = 0; j < 8; ++j) o[i][j] = 0.f;
    }

    for (int kt = 0; kt < SEQ; kt += 128) {
        // ---------------- S = Q K^T (this 128x128 tile) ----------------
        float s[8][8];
#pragma unroll
        for (int i = 0; i < 8; ++i)
#pragma unroll
            for (int j = 0; j < 8; ++j) s[i][j] = 0.f;

        for (int d0 = 0; d0 < HDIM; d0 += 16) {
#pragma unroll
            for (int t = 0; t < 2; ++t) {
                int idx = tid * 2 + t;
                int row = idx >> 2;
                int kq  = idx & 3;
                float4 qa = *(const float4*)(Qp + (size_t)row * HDIM + d0 + kq*4);
                float4 kb = *(const float4*)(Kp + (size_t)(kt + row) * HDIM + d0 + kq*4);
                As[(kq*4+0)*128 + row] = qa.x; As[(kq*4+1)*128 + row] = qa.y;
                As[(kq*4+2)*128 + row] = qa.z; As[(kq*4+3)*128 + row] = qa.w;
                Bs[(kq*4+0)*128 + row] = kb.x; Bs[(kq*4+1)*128 + row] = kb.y;
                Bs[(kq*4+2)*128 + row] = kb.z; Bs[(kq*4+3)*128 + row] = kb.w;
            }
            __syncthreads();
#pragma unroll
            for (int kk = 0; kk < 16; ++kk) {
                float4 a0 = *(const float4*)(As + kk*128 + ty*4);
                float4 a1 = *(const float4*)(As + kk*128 + 64 + ty*4);
                float4 b0 = *(const float4*)(Bs + kk*128 + tx*4);
                float4 b1 = *(const float4*)(Bs + kk*128 + 64 + tx*4);
                float av[8] = {a0.x,a0.y,a0.z,a0.w,a1.x,a1.y,a1.z,a1.w};
                float bv[8] = {b0.x,b0.y,b0.z,b0.w,b1.x,b1.y,b1.z,b1.w};
#pragma unroll
                for (int i = 0; i < 8; ++i)
#pragma unroll
                    for (int j = 0; j < 8; ++j)
                        s[i][j] += av[i] * bv[j];
            }
            __syncthreads();
        }

        // ---------------- online softmax (rows owned by ty; reduce over tx) --
#pragma unroll
        for (int i = 0; i < 8; ++i) {
            float rmax = -1e30f;
#pragma unroll
            for (int j = 0; j < 8; ++j) { s[i][j] *= scale; rmax = fmaxf(rmax, s[i][j]); }
#pragma unroll
            for (int off = 8; off > 0; off >>= 1)
                rmax = fmaxf(rmax, __shfl_xor_sync(0xffffffffu, rmax, off, 16));
            float mnew = fmaxf(m[i], rmax);
            float corr = __expf(m[i] - mnew);
            float rsum = 0.f;
#pragma unroll
            for (int j = 0; j < 8; ++j) { s[i][j] = __expf(s[i][j] - mnew); rsum += s[i][j]; }
#pragma unroll
            for (int off = 8; off > 0; off >>= 1)
                rsum += __shfl_xor_sync(0xffffffffu, rsum, off, 16);
            m[i] = mnew;
            l[i] = l[i] * corr + rsum;
#pragma unroll
            for (int j = 0; j < 8; ++j) o[i][j] *= corr;
        }

        // ---------------- stage P^T to smem + load V tile ----------------
#pragma unroll
        for (int jj = 0; jj < 8; ++jj) {
            int c = (jj < 4) ? (tx*4 + jj) : (60 + tx*4 + jj);
            float4 p0 = make_float4(s[0][jj], s[1][jj], s[2][jj], s[3][jj]);
            float4 p1 = make_float4(s[4][jj], s[5][jj], s[6][jj], s[7][jj]);
            *(float4*)(Ps + c*PS_PITCH + ty*4)      = p0;
            *(float4*)(Ps + c*PS_PITCH + 64 + ty*4) = p1;
        }
#pragma unroll
        for (int t = 0; t < 16; ++t) {                 // 4096 float4 / 256 thr
            int idx = t * 256 + tid;
            int row = idx >> 5;
            int cq  = idx & 31;
            *(float4*)(Vs + row*128 + cq*4) =
                *(const float4*)(Vp + (size_t)(kt + row) * HDIM + cq*4);
        }
        __syncthreads();

        // ---------------- O += P V ----------------
#pragma unroll 4
        for (int kk = 0; kk < 128; ++kk) {
            float4 a0 = *(const float4*)(Ps + kk*PS_PITCH + ty*4);
            float4 a1 = *(const float4*)(Ps + kk*PS_PITCH + 64 + ty*4);
            float4 b0 = *(const float4*)(Vs + kk*128 + tx*4);
            float4 b1 = *(const float4*)(Vs + kk*128 + 64 + tx*4);
            float av[8] = {a0.x,a0.y,a0.z,a0.w,a1.x,a1.y,a1.z,a1.w};
            float bv[8] = {b0.x,b0.y,b0.z,b0.w,b1.x,b1.y,b1.z,b1.w};
#pragma unroll
            for (int i = 0; i < 8; ++i)
#pragma unroll
                for (int j = 0; j < 8; ++j)
                    o[i][j] += av[i] * bv[j];
        }
        __syncthreads();
    }

    // ---------------- finalize & write to [B, L, H, D] ----------------
    const int b = bh >> 4, h = bh & 15;
#pragma unroll
    for (int i = 0; i < 8; ++i) {
        int rloc = (i < 4) ? (ty*4 + i) : (60 + ty*4 + i);
        int lg = qt * 128 + rloc;
        float inv = 1.f / l[i];
        size_t base = ((size_t)((b * SEQ + lg) * HEADS + h)) * HDIM;
#pragma unroll
        for (int jg = 0; jg < 2; ++jg) {
            float4 v4 = make_float4(o[i][jg*4+0]*inv, o[i][jg*4+1]*inv,
                                    o[i][jg*4+2]*inv, o[i][jg*4+3]*inv);
            *(float4*)(AO + base + jg*64 + tx*4) = v4;
        }
    }
}

// ============================================================================
// launch
// ============================================================================
extern "C" void kernel_launch(void* const* d_in, const int* in_sizes, int n_in,
                              void* d_out, int out_size)
{
    (void)in_sizes; (void)n_in; (void)out_size;
    const float* x    = (const float*)d_in[0];
    const float* cs   = (const float*)d_in[1];
    const float* sn   = (const float*)d_in[2];
    const float* wqkv = (const float*)d_in[3];
    const float* wout = (const float*)d_in[4];
    float* out = (float*)d_out;

    float *qkv, *q, *k, *v, *ao;
    cudaGetSymbolAddress((void**)&qkv, g_qkv);
    cudaGetSymbolAddress((void**)&q,   g_q);
    cudaGetSymbolAddress((void**)&k,   g_k);
    cudaGetSymbolAddress((void**)&v,   g_v);
    cudaGetSymbolAddress((void**)&ao,  g_ao);

    cudaFuncSetAttribute(attn_kernel,
                         cudaFuncAttributeMaxDynamicSharedMemorySize, ATT_SMEM);

    dim3 blk(256);
    // 1) qkv = x @ w_qkv^T   [8192, 6144]
    sgemm_nt<<<dim3(NQKV/128, MROWS/128), blk>>>(x, wqkv, qkv, MROWS, NQKV, HIDDEN);
    // 2) RoPE + split to [B,H,L,D]
    rope_split<<<(BATCH*SEQ*HEADS*64)/256, blk>>>(qkv, cs, sn, q, k, v);
    // 3) attention -> [B,L,H*D]
    attn_kernel<<<dim3(SEQ/128, BATCH*HEADS), blk, ATT_SMEM>>>(q, k, v, ao);
    // 4) out = ao @ w_out^T
    sgemm_nt<<<dim3(HIDDEN/128, MROWS/128), blk>>>(ao, wout, out, MROWS, HIDDEN, HIDDEN);
}

// round 14
// speedup vs baseline: 1.0008x; 1.0006x over previous
#include <cuda_runtime.h>

#define HIDDEN 2048
#define HEADS  16
#define HDIM   128
#define BATCH  4
#define SEQ    2048
#define MROWS  (BATCH*SEQ)        /* 8192 */
#define NQKV   (3*HIDDEN)         /* 6144 */

// ---------------- scratch (device globals; no runtime allocation) ----------
__device__ float g_qkv[(size_t)MROWS * NQKV];                 // 201 MB
__device__ float g_q  [(size_t)BATCH*HEADS*SEQ*HDIM];         // 67 MB  [B,H,L,D]
__device__ float g_k  [(size_t)BATCH*HEADS*SEQ*HDIM];
__device__ float g_v  [(size_t)BATCH*HEADS*SEQ*HDIM];
__device__ float g_ao [(size_t)MROWS * HIDDEN];               // [B,L,H*D]

// ============================================================================
// SGEMM (NT): C[m][n] = sum_k A[m*K+k] * B[n*K+k]
// 128x128 block tile, BK=16, 256 threads, 8x8 per-thread register tile.
// Both A and B tiles stored k-major-transposed in smem: s[kk][row].
// Requires M%128==0, N%128==0, K%16==0 (true for all our shapes).
// ============================================================================
__global__ __launch_bounds__(256, 2)
void sgemm_nt(const float* __restrict__ A, const float* __restrict__ B,
              float* __restrict__ C, int M, int N, int K)
{
    __shared__ float As[16 * 128];
    __shared__ float Bs[16 * 128];

    const int tid = threadIdx.x;
    const int ty  = tid >> 4;      // 0..15
    const int tx  = tid & 15;      // 0..15
    const int m0  = blockIdx.y * 128;
    const int n0  = blockIdx.x * 128;

    float acc[8][8];
#pragma unroll
    for (int i = 0; i < 8; ++i)
#pragma unroll
        for (int j = 0; j < 8; ++j) acc[i][j] = 0.f;

    for (int k0 = 0; k0 < K; k0 += 16) {
        // cooperative load: tile is [128 rows][16 k]; 512 float4 per tensor
#pragma unroll
        for (int t = 0; t < 2; ++t) {
            int idx = tid * 2 + t;
            int row = idx >> 2;
            int kq  = idx & 3;
            float4 av = *(const float4*)(A + (size_t)(m0 + row) * K + k0 + kq * 4);
            float4 bv = *(const float4*)(B + (size_t)(n0 + row) * K + k0 + kq * 4);
            As[(kq*4+0)*128 + row] = av.x; As[(kq*4+1)*128 + row] = av.y;
            As[(kq*4+2)*128 + row] = av.z; As[(kq*4+3)*128 + row] = av.w;
            Bs[(kq*4+0)*128 + row] = bv.x; Bs[(kq*4+1)*128 + row] = bv.y;
            Bs[(kq*4+2)*128 + row] = bv.z; Bs[(kq*4+3)*128 + row] = bv.w;
        }
        __syncthreads();
#pragma unroll
        for (int kk = 0; kk < 16; ++kk) {
            float4 a0 = *(const float4*)(As + kk*128 + ty*4);
            float4 a1 = *(const float4*)(As + kk*128 + 64 + ty*4);
            float4 b0 = *(const float4*)(Bs + kk*128 + tx*4);
            float4 b1 = *(const float4*)(Bs + kk*128 + 64 + tx*4);
            float av[8] = {a0.x,a0.y,a0.z,a0.w,a1.x,a1.y,a1.z,a1.w};
            float bv[8] = {b0.x,b0.y,b0.z,b0.w,b1.x,b1.y,b1.z,b1.w};
#pragma unroll
            for (int i = 0; i < 8; ++i)
#pragma unroll
                for (int j = 0; j < 8; ++j)
                    acc[i][j] += av[i] * bv[j];
        }
        __syncthreads();
    }

#pragma unroll
    for (int i = 0; i < 8; ++i) {
        int r = m0 + ((i < 4) ? (ty*4 + i) : (60 + ty*4 + i));  // i>=4 -> 64+ty*4+(i-4)
#pragma unroll
        for (int jg = 0; jg < 2; ++jg) {
            float4 v = make_float4(acc[i][jg*4+0], acc[i][jg*4+1],
                                   acc[i][jg*4+2], acc[i][jg*4+3]);
            *(float4*)(C + (size_t)r * N + n0 + jg*64 + tx*4) = v;
        }
    }
}

// ============================================================================
// RoPE + split qkv[B,L,3*HIDDEN] -> Q,K (rotated), V  in [B,H,L,D]
// One thread per (b,h,l,d0) with d0 in [0,64): handles the paired element too.
// ============================================================================
__global__ __launch_bounds__(256)
void rope_split(const float* __restrict__ qkv,
                const float* __restrict__ cs, const float* __restrict__ sn,
                float* __restrict__ Q, float* __restrict__ Kd,
                float* __restrict__ V)
{
    int idx = blockIdx.x * blockDim.x + threadIdx.x;     // B*L*H*64 threads
    int d0 = idx & 63;
    int h  = (idx >> 6) & 15;
    int l  = (idx >> 10) & 2047;
    int b  = idx >> 21;

    const float* row = qkv + (size_t)(b * SEQ + l) * NQKV;
    float c0 = cs[l*HDIM + d0],      s0 = sn[l*HDIM + d0];
    float c1 = cs[l*HDIM + d0 + 64], s1 = sn[l*HDIM + d0 + 64];

    size_t obase = ((size_t)((b*HEADS + h) * SEQ + l)) * HDIM;

    float q0 = row[h*HDIM + d0], q1 = row[h*HDIM + d0 + 64];
    Q[obase + d0]      = q0 * c0 - q1 * s0;
    Q[obase + d0 + 64] = q1 * c1 + q0 * s1;

    float k0 = row[HIDDEN + h*HDIM + d0], k1 = row[HIDDEN + h*HDIM + d0 + 64];
    Kd[obase + d0]      = k0 * c0 - k1 * s0;
    Kd[obase + d0 + 64] = k1 * c1 + k0 * s1;

    V[obase + d0]      = row[2*HIDDEN + h*HDIM + d0];
    V[obase + d0 + 64] = row[2*HIDDEN + h*HDIM + d0 + 64];
}

// ============================================================================
// Flash attention, fp32. grid = (SEQ/128, B*H), 256 threads.
// Q tile 128 rows, KV tile 128 rows, D=128 streamed with BK=16 for S = Q K^T.
// Online softmax; P staged transposed in smem (pitch 132 to cut STS conflicts);
// O = P V accumulated in registers (8x8/thread). Output written in [B,L,H,D].
// Dynamic smem = 149504 B.
// ============================================================================
#define PS_PITCH 132
#define ATT_SMEM ((2*16*128 + 128*PS_PITCH + 128*128) * 4)

__global__ __launch_bounds__(256)
void attn_kernel(const float* __restrict__ Q, const float* __restrict__ K,
                 const float* __restrict__ V, float* __restrict__ AO)
{
    extern __shared__ float sm[];
    float* As = sm;                       // [16][128]  Q d-slice, transposed
    float* Bs = As + 16*128;              // [16][128]  K d-slice, transposed
    float* Ps = Bs + 16*128;              // [128][132] P transposed: Ps[k][r]
    float* Vs = Ps + 128*PS_PITCH;        // [128][128] V tile: Vs[k][c]

    const int bh = blockIdx.y;
    const int qt = blockIdx.x;
    const float* Qp = Q + (size_t)bh * SEQ * HDIM + (size_t)qt * 128 * HDIM;
    const float* Kp = K + (size_t)bh * SEQ * HDIM;
    const float* Vp = V + (size_t)bh * SEQ * HDIM;

    const int tid = threadIdx.x;
    const int ty  = tid >> 4;
    const int tx  = tid & 15;

    const float scale = 0.08838834764831845f;   // 1/sqrt(128)

    float m[8], l[8], o[8][8];
#pragma unroll
    for (int i = 0; i < 8; ++i) {
        m[i] = -1e30f; l[i] = 0.f;
#pragma unroll
        for (int j = 0; j < 8; ++j) o[i][j] = 0.f;
    }

    for (int kt = 0; kt < SEQ; kt += 128) {
        // ---------------- S = Q K^T (this 128x128 tile) ----------------
        float s[8][8];
#pragma unroll
        for (int i = 0; i < 8; ++i)
#pragma unroll
            for (int j = 0; j < 8; ++j) s[i][j] = 0.f;

        for (int d0 = 0; d0 < HDIM; d0 += 16) {
#pragma unroll
            for (int t = 0; t < 2; ++t) {
                int idx = tid * 2 + t;
                int row = idx >> 2;
                int kq  = idx & 3;
                float4 qa = *(const float4*)(Qp + (size_t)row * HDIM + d0 + kq*4);
                float4 kb = *(const float4*)(Kp + (size_t)(kt + row) * HDIM + d0 + kq*4);
                As[(kq*4+0)*128 + row] = qa.x; As[(kq*4+1)*128 + row] = qa.y;
                As[(kq*4+2)*128 + row] = qa.z; As[(kq*4+3)*128 + row] = qa.w;
                Bs[(kq*4+0)*128 + row] = kb.x; Bs[(kq*4+1)*128 + row] = kb.y;
                Bs[(kq*4+2)*128 + row] = kb.z; Bs[(kq*4+3)*128 + row] = kb.w;
            }
            __syncthreads();
#pragma unroll
            for (int kk = 0; kk < 16; ++kk) {
                float4 a0 = *(const float4*)(As + kk*128 + ty*4);
                float4 a1 = *(const float4*)(As + kk*128 + 64 + ty*4);
                float4 b0 = *(const float4*)(Bs + kk*128 + tx*4);
                float4 b1 = *(const float4*)(Bs + kk*128 + 64 + tx*4);
                float av[8] = {a0.x,a0.y,a0.z,a0.w,a1.x,a1.y,a1.z,a1.w};
                float bv[8] = {b0.x,b0.y,b0.z,b0.w,b1.x,b1.y,b1.z,b1.w};
#pragma unroll
                for (int i = 0; i < 8; ++i)
#pragma unroll
                    for (int j = 0; j < 8; ++j)
                        s[i][j] += av[i] * bv[j];
            }
            __syncthreads();
        }

        // ---------------- online softmax (rows owned by ty; reduce over tx) --
#pragma unroll
        for (int i = 0; i < 8; ++i) {
            float rmax = -1e30f;
#pragma unroll
            for (int j = 0; j < 8; ++j) { s[i][j] *= scale; rmax = fmaxf(rmax, s[i][j]); }
#pragma unroll
            for (int off = 8; off > 0; off >>= 1)
                rmax = fmaxf(rmax, __shfl_xor_sync(0xffffffffu, rmax, off, 16));
            float mnew = fmaxf(m[i], rmax);
            float corr = __expf(m[i] - mnew);
            float rsum = 0.f;
#pragma unroll
            for (int j = 0; j < 8; ++j) { s[i][j] = __expf(s[i][j] - mnew); rsum += s[i][j]; }
#pragma unroll
            for (int off = 8; off > 0; off >>= 1)
                rsum += __shfl_xor_sync(0xffffffffu, rsum, off, 16);
            m[i] = mnew;
            l[i] = l[i] * corr + rsum;
#pragma unroll
            for (int j = 0; j < 8; ++j) o[i][j] *= corr;
        }

        // ---------------- stage P^T to smem + load V tile ----------------
#pragma unroll
        for (int jj = 0; jj < 8; ++jj) {
            int c = (jj < 4) ? (tx*4 + jj) : (60 + tx*4 + jj);
            float4 p0 = make_float4(s[0][jj], s[1][jj], s[2][jj], s[3][jj]);
            float4 p1 = make_float4(s[4][jj], s[5][jj], s[6][jj], s[7][jj]);
            *(float4*)(Ps + c*PS_PITCH + ty*4)      = p0;
            *(float4*)(Ps + c*PS_PITCH + 64 + ty*4) = p1;
        }
#pragma unroll
        for (int t = 0; t < 16; ++t) {                 // 4096 float4 / 256 thr
            int idx = t * 256 + tid;
            int row = idx >> 5;
            int cq  = idx & 31;
            *(float4*)(Vs + row*128 + cq*4) =
                *(const float4*)(Vp + (size_t)(kt + row) * HDIM + cq*4);
        }
        __syncthreads();

        // ---------------- O += P V ----------------
#pragma unroll 4
        for (int kk = 0; kk < 128; ++kk) {
            float4 a0 = *(const float4*)(Ps + kk*PS_PITCH + ty*4);
            float4 a1 = *(const float4*)(Ps + kk*PS_PITCH + 64 + ty*4);
            float4 b0 = *(const float4*)(Vs + kk*128 + tx*4);
            float4 b1 = *(const float4*)(Vs + kk*128 + 64 + tx*4);
            float av[8] = {a0.x,a0.y,a0.z,a0.w,a1.x,a1.y,a1.z,a1.w};
            float bv[8] = {b0.x,b0.y,b0.z,b0.w,b1.x,b1.y,b1.z,b1.w};
#pragma unroll
            for (int i = 0; i < 8; ++i)
#pragma unroll
                for (int j = 0; j < 8; ++j)
                    o[i][j] += av[i] * bv[j];
        }
        __syncthreads();
    }

    // ---------------- finalize & write to [B, L, H, D] ----------------
    const int b = bh >> 4, h = bh & 15;
#pragma unroll
    for (int i = 0; i < 8; ++i) {
        int rloc = (i < 4) ? (ty*4 + i) : (60 + ty*4 + i);
        int lg = qt * 128 + rloc;
        float inv = 1.f / l[i];
        size_t base = ((size_t)((b * SEQ + lg) * HEADS + h)) * HDIM;
#pragma unroll
        for (int jg = 0; jg < 2; ++jg) {
            float4 v4 = make_float4(o[i][jg*4+0]*inv, o[i][jg*4+1]*inv,
                                    o[i][jg*4+2]*inv, o[i][jg*4+3]*inv);
            *(float4*)(AO + base + jg*64 + tx*4) = v4;
        }
    }
}

// ============================================================================
// launch
// ============================================================================
extern "C" void kernel_launch(void* const* d_in, const int* in_sizes, int n_in,
                              void* d_out, int out_size)
{
    (void)in_sizes; (void)n_in; (void)out_size;
    const float* x    = (const float*)d_in[0];
    const float* cs   = (const float*)d_in[1];
    const float* sn   = (const float*)d_in[2];
    const float* wqkv = (const float*)d_in[3];
    const float* wout = (const float*)d_in[4];
    float* out = (float*)d_out;

    float *qkv, *q, *k, *v, *ao;
    cudaGetSymbolAddress((void**)&qkv, g_qkv);
    cudaGetSymbolAddress((void**)&q,   g_q);
    cudaGetSymbolAddress((void**)&k,   g_k);
    cudaGetSymbolAddress((void**)&v,   g_v);
    cudaGetSymbolAddress((void**)&ao,  g_ao);

    cudaFuncSetAttribute(attn_kernel,
                         cudaFuncAttributeMaxDynamicSharedMemorySize, ATT_SMEM);

    dim3 blk(256);
    // 1) qkv = x @ w_qkv^T   [8192, 6144]
    sgemm_nt<<<dim3(NQKV/128, MROWS/128), blk>>>(x, wqkv, qkv, MROWS, NQKV, HIDDEN);
    // 2) RoPE + split to [B,H,L,D]
    rope_split<<<(BATCH*SEQ*HEADS*64)/256, blk>>>(qkv, cs, sn, q, k, v);
    // 3) attention -> [B,L,H*D]
    attn_kernel<<<dim3(SEQ/128, BATCH*HEADS), blk, ATT_SMEM>>>(q, k, v, ao);
    // 4) out = ao @ w_out^T
    sgemm_nt<<<dim3(HIDDEN/128, MROWS/128), blk>>>(ao, wout, out, MROWS, HIDDEN, HIDDEN);
}

// round 15
// speedup vs baseline: 1.0010x; 1.0002x over previous
#include <cuda_runtime.h>

#define HIDDEN 2048
#define HEADS  16
#define HDIM   128
#define BATCH  4
#define SEQ    2048
#define MROWS  (BATCH*SEQ)        /* 8192 */
#define NQKV   (3*HIDDEN)         /* 6144 */

// ---------------- scratch (device globals; no runtime allocation) ----------
__device__ float g_qkv[(size_t)MROWS * NQKV];                 // 201 MB
__device__ float g_q  [(size_t)BATCH*HEADS*SEQ*HDIM];         // 67 MB  [B,H,L,D]
__device__ float g_k  [(size_t)BATCH*HEADS*SEQ*HDIM];
__device__ float g_v  [(size_t)BATCH*HEADS*SEQ*HDIM];
__device__ float g_ao [(size_t)MROWS * HIDDEN];               // [B,L,H*D]

// ============================================================================
// SGEMM (NT): C[m][n] = sum_k A[m*K+k] * B[n*K+k]
// 128x128 block tile, BK=16, 256 threads, 8x8 per-thread register tile.
// Both A and B tiles stored k-major-transposed in smem: s[kk][row].
// Requires M%128==0, N%128==0, K%16==0 (true for all our shapes).
// ============================================================================
__global__ __launch_bounds__(256, 2)
void sgemm_nt(const float* __restrict__ A, const float* __restrict__ B,
              float* __restrict__ C, int M, int N, int K)
{
    __shared__ float As[16 * 128];
    __shared__ float Bs[16 * 128];

    const int tid = threadIdx.x;
    const int ty  = tid >> 4;      // 0..15
    const int tx  = tid & 15;      // 0..15
    const int m0  = blockIdx.y * 128;
    const int n0  = blockIdx.x * 128;

    float acc[8][8];
#pragma unroll
    for (int i = 0; i < 8; ++i)
#pragma unroll
        for (int j = 0; j < 8; ++j) acc[i][j] = 0.f;

    for (int k0 = 0; k0 < K; k0 += 16) {
        // cooperative load: tile is [128 rows][16 k]; 512 float4 per tensor
#pragma unroll
        for (int t = 0; t < 2; ++t) {
            int idx = tid * 2 + t;
            int row = idx >> 2;
            int kq  = idx & 3;
            float4 av = *(const float4*)(A + (size_t)(m0 + row) * K + k0 + kq * 4);
            float4 bv = *(const float4*)(B + (size_t)(n0 + row) * K + k0 + kq * 4);
            As[(kq*4+0)*128 + row] = av.x; As[(kq*4+1)*128 + row] = av.y;
            As[(kq*4+2)*128 + row] = av.z; As[(kq*4+3)*128 + row] = av.w;
            Bs[(kq*4+0)*128 + row] = bv.x; Bs[(kq*4+1)*128 + row] = bv.y;
            Bs[(kq*4+2)*128 + row] = bv.z; Bs[(kq*4+3)*128 + row] = bv.w;
        }
        __syncthreads();
#pragma unroll
        for (int kk = 0; kk < 16; ++kk) {
            float4 a0 = *(const float4*)(As + kk*128 + ty*4);
            float4 a1 = *(const float4*)(As + kk*128 + 64 + ty*4);
            float4 b0 = *(const float4*)(Bs + kk*128 + tx*4);
            float4 b1 = *(const float4*)(Bs + kk*128 + 64 + tx*4);
            float av[8] = {a0.x,a0.y,a0.z,a0.w,a1.x,a1.y,a1.z,a1.w};
            float bv[8] = {b0.x,b0.y,b0.z,b0.w,b1.x,b1.y,b1.z,b1.w};
#pragma unroll
            for (int i = 0; i < 8; ++i)
#pragma unroll
                for (int j = 0; j < 8; ++j)
                    acc[i][j] += av[i] * bv[j];
        }
        __syncthreads();
    }

#pragma unroll
    for (int i = 0; i < 8; ++i) {
        int r = m0 + ((i < 4) ? (ty*4 + i) : (60 + ty*4 + i));  // i>=4 -> 64+ty*4+(i-4)
#pragma unroll
        for (int jg = 0; jg < 2; ++jg) {
            float4 v = make_float4(acc[i][jg*4+0], acc[i][jg*4+1],
                                   acc[i][jg*4+2], acc[i][jg*4+3]);
            *(float4*)(C + (size_t)r * N + n0 + jg*64 + tx*4) = v;
        }
    }
}

// ============================================================================
// RoPE + split qkv[B,L,3*HIDDEN] -> Q,K (rotated), V  in [B,H,L,D]
// One thread per (b,h,l,d0) with d0 in [0,64): handles the paired element too.
// ============================================================================
__global__ __launch_bounds__(256)
void rope_split(const float* __restrict__ qkv,
                const float* __restrict__ cs, const float* __restrict__ sn,
                float* __restrict__ Q, float* __restrict__ Kd,
                float* __restrict__ V)
{
    int idx = blockIdx.x * blockDim.x + threadIdx.x;     // B*L*H*64 threads
    int d0 = idx & 63;
    int h  = (idx >> 6) & 15;
    int l  = (idx >> 10) & 2047;
    int b  = idx >> 21;

    const float* row = qkv + (size_t)(b * SEQ + l) * NQKV;
    float c0 = cs[l*HDIM + d0],      s0 = sn[l*HDIM + d0];
    float c1 = cs[l*HDIM + d0 + 64], s1 = sn[l*HDIM + d0 + 64];

    size_t obase = ((size_t)((b*HEADS + h) * SEQ + l)) * HDIM;

    float q0 = row[h*HDIM + d0], q1 = row[h*HDIM + d0 + 64];
    Q[obase + d0]      = q0 * c0 - q1 * s0;
    Q[obase + d0 + 64] = q1 * c1 + q0 * s1;

    float k0 = row[HIDDEN + h*HDIM + d0], k1 = row[HIDDEN + h*HDIM + d0 + 64];
    Kd[obase + d0]      = k0 * c0 - k1 * s0;
    Kd[obase + d0 + 64] = k1 * c1 + k0 * s1;

    V[obase + d0]      = row[2*HIDDEN + h*HDIM + d0];
    V[obase + d0 + 64] = row[2*HIDDEN + h*HDIM + d0 + 64];
}

// ============================================================================
// Flash attention, fp32. grid = (SEQ/128, B*H), 256 threads.
// Q tile 128 rows, KV tile 128 rows, D=128 streamed with BK=16 for S = Q K^T.
// Online softmax; P staged transposed in smem (pitch 132 to cut STS conflicts);
// O = P V accumulated in registers (8x8/thread). Output written in [B,L,H,D].
// Dynamic smem = 149504 B.
// ============================================================================
#define PS_PITCH 132
#define ATT_SMEM ((2*16*128 + 128*PS_PITCH + 128*128) * 4)

__global__ __launch_bounds__(256)
void attn_kernel(const float* __restrict__ Q, const float* __restrict__ K,
                 const float* __restrict__ V, float* __restrict__ AO)
{
    extern __shared__ float sm[];
    float* As = sm;                       // [16][128]  Q d-slice, transposed
    float* Bs = As + 16*128;              // [16][128]  K d-slice, transposed
    float* Ps = Bs + 16*128;              // [128][132] P transposed: Ps[k][r]
    float* Vs = Ps + 128*PS_PITCH;        // [128][128] V tile: Vs[k][c]

    const int bh = blockIdx.y;
    const int qt = blockIdx.x;
    const float* Qp = Q + (size_t)bh * SEQ * HDIM + (size_t)qt * 128 * HDIM;
    const float* Kp = K + (size_t)bh * SEQ * HDIM;
    const float* Vp = V + (size_t)bh * SEQ * HDIM;

    const int tid = threadIdx.x;
    const int ty  = tid >> 4;
    const int tx  = tid & 15;

    const float scale = 0.08838834764831845f;   // 1/sqrt(128)

    float m[8], l[8], o[8][8];
#pragma unroll
    for (int i = 0; i < 8; ++i) {
        m[i] = -1e30f; l[i] = 0.f;
#pragma unroll
        for (int j = 0; j < 8; ++j) o[i][j] = 0.f;
    }

    for (int kt = 0; kt < SEQ; kt += 128) {
        // ---------------- S = Q K^T (this 128x128 tile) ----------------
        float s[8][8];
#pragma unroll
        for (int i = 0; i < 8; ++i)
#pragma unroll
            for (int j = 0; j < 8; ++j) s[i][j] = 0.f;

        for (int d0 = 0; d0 < HDIM; d0 += 16) {
#pragma unroll
            for (int t = 0; t < 2; ++t) {
                int idx = tid * 2 + t;
                int row = idx >> 2;
                int kq  = idx & 3;
                float4 qa = *(const float4*)(Qp + (size_t)row * HDIM + d0 + kq*4);
                float4 kb = *(const float4*)(Kp + (size_t)(kt + row) * HDIM + d0 + kq*4);
                As[(kq*4+0)*128 + row] = qa.x; As[(kq*4+1)*128 + row] = qa.y;
                As[(kq*4+2)*128 + row] = qa.z; As[(kq*4+3)*128 + row] = qa.w;
                Bs[(kq*4+0)*128 + row] = kb.x; Bs[(kq*4+1)*128 + row] = kb.y;
                Bs[(kq*4+2)*128 + row] = kb.z; Bs[(kq*4+3)*128 + row] = kb.w;
            }
            __syncthreads();
#pragma unroll
            for (int kk = 0; kk < 16; ++kk) {
                float4 a0 = *(const float4*)(As + kk*128 + ty*4);
                float4 a1 = *(const float4*)(As + kk*128 + 64 + ty*4);
                float4 b0 = *(const float4*)(Bs + kk*128 + tx*4);
                float4 b1 = *(const float4*)(Bs + kk*128 + 64 + tx*4);
                float av[8] = {a0.x,a0.y,a0.z,a0.w,a1.x,a1.y,a1.z,a1.w};
                float bv[8] = {b0.x,b0.y,b0.z,b0.w,b1.x,b1.y,b1.z,b1.w};
#pragma unroll
                for (int i = 0; i < 8; ++i)
#pragma unroll
                    for (int j = 0; j < 8; ++j)
                        s[i][j] += av[i] * bv[j];
            }
            __syncthreads();
        }

        // ---------------- online softmax (rows owned by ty; reduce over tx) --
#pragma unroll
        for (int i = 0; i < 8; ++i) {
            float rmax = -1e30f;
#pragma unroll
            for (int j = 0; j < 8; ++j) { s[i][j] *= scale; rmax = fmaxf(rmax, s[i][j]); }
#pragma unroll
            for (int off = 8; off > 0; off >>= 1)
                rmax = fmaxf(rmax, __shfl_xor_sync(0xffffffffu, rmax, off, 16));
            float mnew = fmaxf(m[i], rmax);
            float corr = __expf(m[i] - mnew);
            float rsum = 0.f;
#pragma unroll
            for (int j = 0; j < 8; ++j) { s[i][j] = __expf(s[i][j] - mnew); rsum += s[i][j]; }
#pragma unroll
            for (int off = 8; off > 0; off >>= 1)
                rsum += __shfl_xor_sync(0xffffffffu, rsum, off, 16);
            m[i] = mnew;
            l[i] = l[i] * corr + rsum;
#pragma unroll
            for (int j = 0; j < 8; ++j) o[i][j] *= corr;
        }

        // ---------------- stage P^T to smem + load V tile ----------------
#pragma unroll
        for (int jj = 0; jj < 8; ++jj) {
            int c = (jj < 4) ? (tx*4 + jj) : (60 + tx*4 + jj);
            float4 p0 = make_float4(s[0][jj], s[1][jj], s[2][jj], s[3][jj]);
            float4 p1 = make_float4(s[4][jj], s[5][jj], s[6][jj], s[7][jj]);
            *(float4*)(Ps + c*PS_PITCH + ty*4)      = p0;
            *(float4*)(Ps + c*PS_PITCH + 64 + ty*4) = p1;
        }
#pragma unroll
        for (int t = 0; t < 16; ++t) {                 // 4096 float4 / 256 thr
            int idx = t * 256 + tid;
            int row = idx >> 5;
            int cq  = idx & 31;
            *(float4*)(Vs + row*128 + cq*4) =
                *(const float4*)(Vp + (size_t)(kt + row) * HDIM + cq*4);
        }
        __syncthreads();

        // ---------------- O += P V ----------------
#pragma unroll 4
        for (int kk = 0; kk < 128; ++kk) {
            float4 a0 = *(const float4*)(Ps + kk*PS_PITCH + ty*4);
            float4 a1 = *(const float4*)(Ps + kk*PS_PITCH + 64 + ty*4);
            float4 b0 = *(const float4*)(Vs + kk*128 + tx*4);
            float4 b1 = *(const float4*)(Vs + kk*128 + 64 + tx*4);
            float av[8] = {a0.x,a0.y,a0.z,a0.w,a1.x,a1.y,a1.z,a1.w};
            float bv[8] = {b0.x,b0.y,b0.z,b0.w,b1.x,b1.y,b1.z,b1.w};
#pragma unroll
            for (int i = 0; i < 8; ++i)
#pragma unroll
                for (int j = 0; j < 8; ++j)
                    o[i][j] += av[i] * bv[j];
        }
        __syncthreads();
    }

    // ---------------- finalize & write to [B, L, H, D] ----------------
    const int b = bh >> 4, h = bh & 15;
#pragma unroll
    for (int i = 0; i < 8; ++i) {
        int rloc = (i < 4) ? (ty*4 + i) : (60 + ty*4 + i);
        int lg = qt * 128 + rloc;
        float inv = 1.f / l[i];
        size_t base = ((size_t)((b * SEQ + lg) * HEADS + h)) * HDIM;
#pragma unroll
        for (int jg = 0; jg < 2; ++jg) {
            float4 v4 = make_float4(o[i][jg*4+0]*inv, o[i][jg*4+1]*inv,
                                    o[i][jg*4+2]*inv, o[i][jg*4+3]*inv);
            *(float4*)(AO + base + jg*64 + tx*4) = v4;
        }
    }
}

// ============================================================================
// launch
// ============================================================================
extern "C" void kernel_launch(void* const* d_in, const int* in_sizes, int n_in,
                              void* d_out, int out_size)
{
    (void)in_sizes; (void)n_in; (void)out_size;
    const float* x    = (const float*)d_in[0];
    const float* cs   = (const float*)d_in[1];
    const float* sn   = (const float*)d_in[2];
    const float* wqkv = (const float*)d_in[3];
    const float* wout = (const float*)d_in[4];
    float* out = (float*)d_out;

    float *qkv, *q, *k, *v, *ao;
    cudaGetSymbolAddress((void**)&qkv, g_qkv);
    cudaGetSymbolAddress((void**)&q,   g_q);
    cudaGetSymbolAddress((void**)&k,   g_k);
    cudaGetSymbolAddress((void**)&v,   g_v);
    cudaGetSymbolAddress((void**)&ao,  g_ao);

    cudaFuncSetAttribute(attn_kernel,
                         cudaFuncAttributeMaxDynamicSharedMemorySize, ATT_SMEM);

    dim3 blk(256);
    // 1) qkv = x @ w_qkv^T   [8192, 6144]
    sgemm_nt<<<dim3(NQKV/128, MROWS/128), blk>>>(x, wqkv, qkv, MROWS, NQKV, HIDDEN);
    // 2) RoPE + split to [B,H,L,D]
    rope_split<<<(BATCH*SEQ*HEADS*64)/256, blk>>>(qkv, cs, sn, q, k, v);
    // 3) attention -> [B,L,H*D]
    attn_kernel<<<dim3(SEQ/128, BATCH*HEADS), blk, ATT_SMEM>>>(q, k, v, ao);
    // 4) out = ao @ w_out^T
    sgemm_nt<<<dim3(HIDDEN/128, MROWS/128), blk>>>(ao, wout, out, MROWS, HIDDEN, HIDDEN);
}